// round 11
// baseline (speedup 1.0000x reference)
#include <cuda_runtime.h>
#include <math.h>

// Problem shape: B=16, S=2048, D=768
#define MAXB 16
#define MAXS 2048
#define MAXD 768
#define NCHUNK 16   // o-dim chunks for fuse partials

// Scratch (device globals — no allocation allowed)
__device__ float g_part[NCHUNK * MAXD * 3];  // fuse partials [chunk][p]
__device__ float g_w2[MAXD * 3];             // fused conv*linear weights [i*3+k]
__device__ float g_c;                        // fused bias
__device__ float g_z0[MAXB * MAXS];          // per-row dot with w2[:,k]
__device__ float g_z1[MAXB * MAXS];
__device__ float g_z2[MAXB * MAXS];
__device__ float g_alpha[MAXB * MAXS];
__device__ int   g_Ft[MAXB * MAXS];          // fire time indices (compacted)
__device__ float g_Fa1[MAXB * MAXS];         // a1 at fire j
__device__ float g_Fa2[MAXB * MAXS];         // a2 at fire j
__device__ int   g_n[MAXB];

// ---------------------------------------------------------------------------
// Kernel 1a: partial fuse. grid = (9 p-blocks, NCHUNK o-chunks), 256 thr.
// ---------------------------------------------------------------------------
__global__ void k_fuse_part(const float* __restrict__ conv_w,
                            const float* __restrict__ lin_w, int D) {
    const int p = blockIdx.x * 256 + threadIdx.x;     // p = i*3+k
    const int P = D * 3;
    if (p >= P) return;
    const int ch = blockIdx.y;
    const int csz = D / NCHUNK;
    const int o0 = ch * csz;
    float acc = 0.f;
    #pragma unroll 4
    for (int o = o0; o < o0 + csz; o++)
        acc += lin_w[o] * conv_w[(size_t)o * P + p];
    g_part[ch * P + p] = acc;
}

// ---------------------------------------------------------------------------
// Kernel 1b: combine partials (fixed order) + c scalar.
// ---------------------------------------------------------------------------
__global__ void k_fuse_comb(const float* __restrict__ conv_b,
                            const float* __restrict__ lin_w,
                            const float* __restrict__ lin_b, int D) {
    const int P = D * 3;
    if ((int)blockIdx.x == (int)gridDim.x - 1) {
        __shared__ float red[256];
        float s = 0.f;
        for (int o = threadIdx.x; o < D; o += 256) s += lin_w[o] * conv_b[o];
        red[threadIdx.x] = s;
        __syncthreads();
        for (int st = 128; st > 0; st >>= 1) {
            if ((int)threadIdx.x < st) red[threadIdx.x] += red[threadIdx.x + st];
            __syncthreads();
        }
        if (threadIdx.x == 0) g_c = red[0] + lin_b[0];
    } else {
        int p = blockIdx.x * 256 + threadIdx.x;
        if (p < P) {
            float acc = 0.f;
            #pragma unroll
            for (int ch = 0; ch < NCHUNK; ch++) acc += g_part[ch * P + p];
            g_w2[p] = acc;
        }
    }
}

// ---------------------------------------------------------------------------
// Kernel 2: z_k[r] = dot(x[r], w2[:,k]). Warp per row, 8 warps/blk.
// (zero-fill overlap removed — measured net regression in R9/R10)
// ---------------------------------------------------------------------------
__global__ void k_z(const float* __restrict__ x, int S, int D) {
    __shared__ __align__(16) float sw2[3 * MAXD];
    for (int idx = threadIdx.x; idx < D * 3; idx += blockDim.x) {
        int i = idx / 3, k = idx - i * 3;
        sw2[k * D + i] = g_w2[idx];
    }
    __syncthreads();

    const int b = blockIdx.y;
    const int warp = threadIdx.x >> 5, lane = threadIdx.x & 31;
    const int r = blockIdx.x * 8 + warp;
    if (r >= S) return;

    const float4* xr  = (const float4*)(x + ((size_t)b * S + r) * D);
    const float4* w0  = (const float4*)(sw2);
    const float4* w1  = (const float4*)(sw2 + D);
    const float4* w2p = (const float4*)(sw2 + 2 * D);
    float a0 = 0.f, a1 = 0.f, a2 = 0.f;

    if (D == MAXD) {
        float4 xv[6];
        #pragma unroll
        for (int u = 0; u < 6; u++) xv[u] = xr[lane + 32 * u];
        #pragma unroll
        for (int u = 0; u < 6; u++) {
            const int m = lane + 32 * u;
            float4 uu = w0[m];
            a0 += uu.x * xv[u].x + uu.y * xv[u].y + uu.z * xv[u].z + uu.w * xv[u].w;
            float4 vv = w1[m];
            a1 += vv.x * xv[u].x + vv.y * xv[u].y + vv.z * xv[u].z + vv.w * xv[u].w;
            float4 ww = w2p[m];
            a2 += ww.x * xv[u].x + ww.y * xv[u].y + ww.z * xv[u].z + ww.w * xv[u].w;
        }
    } else {
        const int M = D >> 2;
        for (int m = lane; m < M; m += 32) {
            float4 xv = xr[m];
            float4 uu = w0[m];
            a0 += uu.x * xv.x + uu.y * xv.y + uu.z * xv.z + uu.w * xv.w;
            float4 vv = w1[m];
            a1 += vv.x * xv.x + vv.y * xv.y + vv.z * xv.z + vv.w * xv.w;
            float4 ww = w2p[m];
            a2 += ww.x * xv.x + ww.y * xv.y + ww.z * xv.z + ww.w * xv.w;
        }
    }
    #pragma unroll
    for (int o = 16; o > 0; o >>= 1) {
        a0 += __shfl_xor_sync(0xffffffffu, a0, o);
        a1 += __shfl_xor_sync(0xffffffffu, a1, o);
        a2 += __shfl_xor_sync(0xffffffffu, a2, o);
    }
    if (lane == 0) {
        size_t idx = (size_t)b * S + r;
        g_z0[idx] = a0; g_z1[idx] = a1; g_z2[idx] = a2;
    }
}

// ---------------------------------------------------------------------------
// Short-recurrence chain step (validated in R10): on fire the reference's
// a2 = a - fl(1-aacc) equals fl(s1-1) exactly up to 1 ulp (Sterbenz on [1,2)).
// ---------------------------------------------------------------------------
#define CHAINSTEP(aval)                                \
    {   float a   = (aval);                            \
        float s1  = aacc + a;                          \
        float sm1 = s1 - 1.0f;                         \
        bool fire = (s1 >= 1.0f);                      \
        BODY                                           \
        aacc = fire ? sm1 : s1;                        \
        bit++;                                         \
    }
#define CHAIN8(q)  CHAINSTEP((q).x) CHAINSTEP((q).y) CHAINSTEP((q).z) CHAINSTEP((q).w)
#define CHAIN32    { CHAIN8(v0) } { CHAIN8(v1) } { CHAIN8(v2) } { CHAIN8(v3) } \
                   { CHAIN8(v4) } { CHAIN8(v5) } { CHAIN8(v6) } { CHAIN8(v7) }

// ---------------------------------------------------------------------------
// Kernel 3: alpha + CIF scan. KEY CHANGE: alphas are sigmoids => strictly
// positive => the running sum is monotone => over any window, fires = integer
// crossings and aacc_out = fract(aacc_in + sum(window)) in real arithmetic.
// So the serial phase collapses from 2048 element steps to 64 CHUNK steps:
//   Phase B : 64 threads sum their 32 alphas in double (deterministic, exact
//             to ~1e-16 — no float-cumsum drift).
//   Serial  : thread 0: 64x { checkpoint; aacc = t - floor(t) } in double.
//   Phase C1: 64 threads replay chunks in float from checkpoints -> fire masks.
//   Phase C2: after popc prefix, replay again writing records (exact reference
//             formulas a1 = 1-aacc, a2 = a-a1) at compacted positions.
// Divergence vs reference = its own per-step float-rounding walk (~3e-7 per
// inter-fire window) — same class as the alpha-input differences already
// carried with zero fire flips.
// ---------------------------------------------------------------------------
__global__ void k_scan(const int* __restrict__ lens, int S) {
    __shared__ __align__(16) float sa[MAXS];
    __shared__ double sSum[MAXS / 32];
    __shared__ float  sChk[MAXS / 32];
    __shared__ unsigned int sMask[MAXS / 32];
    __shared__ int    sNfb[MAXS / 32];
    const int b = blockIdx.x;
    const int base = b * S;
    const int len = lens[b];
    const float c = g_c;
    const int NC = S >> 5;   // chunks of 32 (S multiple of 32)

    // Phase A: alphas -> smem + g_alpha (exact 0 beyond len)
    for (int t = threadIdx.x; t < S; t += blockDim.x) {
        float a = 0.f;
        if (t < len) {
            float l = c + g_z1[base + t];
            if (t > 0)     l += g_z0[base + t - 1];
            if (t < S - 1) l += g_z2[base + t + 1];
            a = 1.f / (1.f + expf(-l));
        }
        sa[t] = a;
        g_alpha[base + t] = a;
    }
    __syncthreads();

    // Phase B: per-chunk double sums (parallel, deterministic order)
    if ((int)threadIdx.x < NC) {
        const float* p = sa + (threadIdx.x << 5);
        double s = 0.0;
        #pragma unroll
        for (int u = 0; u < 32; u++) s += (double)p[u];
        sSum[threadIdx.x] = s;
    }
    __syncthreads();

    // Serial phase: 64 chunk steps in double
    if (threadIdx.x == 0) {
        double aacc = 0.0;
        for (int cb = 0; cb < NC; cb++) {
            sChk[cb] = (float)aacc;
            double t = aacc + sSum[cb];
            aacc = t - floor(t);
        }
    }
    __syncthreads();

    // Phase C1: parallel float replay -> fire masks
    if ((int)threadIdx.x < NC) {
        const int cb = threadIdx.x;
        float aacc = sChk[cb];
        const float4* q = (const float4*)(sa + (cb << 5));
        float4 v0 = q[0], v1 = q[1], v2 = q[2], v3 = q[3];
        float4 v4 = q[4], v5 = q[5], v6 = q[6], v7 = q[7];
        unsigned int mask = 0u;
        int bit = 0;
        #define BODY mask |= fire ? (1u << bit) : 0u;
        CHAIN32
        #undef BODY
        sMask[cb] = mask;
    }
    __syncthreads();

    // Prefix counts
    if ((int)threadIdx.x < NC) {
        int cnt = 0;
        for (int j = 0; j < (int)threadIdx.x; j++) cnt += __popc(sMask[j]);
        sNfb[threadIdx.x] = cnt;
        if ((int)threadIdx.x == NC - 1)
            g_n[b] = cnt + __popc(sMask[NC - 1]);
    }
    __syncthreads();

    // Phase C2: replay again, write compacted records
    if ((int)threadIdx.x < NC) {
        const int cb = threadIdx.x;
        if (sMask[cb]) {
            float aacc = sChk[cb];
            int pos = base + sNfb[cb];
            const int t0c = cb << 5;
            const float4* q = (const float4*)(sa + t0c);
            float4 v0 = q[0], v1 = q[1], v2 = q[2], v3 = q[3];
            float4 v4 = q[4], v5 = q[5], v6 = q[6], v7 = q[7];
            int bit = 0;
            #define BODY if (fire) { float ra1 = 1.0f - aacc;      \
                                     float ra2 = a - ra1;          \
                                     g_Ft[pos] = t0c + bit;        \
                                     g_Fa1[pos] = ra1;             \
                                     g_Fa2[pos] = ra2; pos++; }
            CHAIN32
            #undef BODY
        }
    }
}

// ---------------------------------------------------------------------------
// Kernel 4: emit (R7 structure — covers ALL rows, no zero-fill elsewhere).
// Block (jb, b) handles 4 output rows. Row j < n: weighted sum over
// t in [F[j-1], F[j]]; rows >= n: zeros.
// ---------------------------------------------------------------------------
__global__ void k_emit(const float* __restrict__ x, float* __restrict__ out,
                       int B, int S, int D, long long out_size) {
    const int b = blockIdx.y;
    const int tid = threadIdx.x;
    const int n = g_n[b];
    const int base = b * S;
    const int j0 = blockIdx.x * 4;

    #pragma unroll
    for (int jj = 0; jj < 4; jj++) {
        const int j = j0 + jj;
        if (j >= S) break;
        float4* orow = (float4*)(out + ((size_t)b * S + j) * D);
        if (j >= n) {
            orow[tid] = make_float4(0.f, 0.f, 0.f, 0.f);
        } else {
            const int t1 = g_Ft[base + j];
            const int t0 = (j == 0) ? 0 : g_Ft[base + j - 1];
            const float wa1 = g_Fa1[base + j];
            const float wa2 = (j == 0) ? 0.f : g_Fa2[base + j - 1];
            float4 acc = make_float4(0.f, 0.f, 0.f, 0.f);
            #pragma unroll 4
            for (int t = t0; t <= t1; t++) {
                float wgt = (t == t1) ? wa1
                          : ((j > 0 && t == t0) ? wa2 : g_alpha[base + t]);
                const float4 h = ((const float4*)(x + ((size_t)b * S + t) * D))[tid];
                acc.x += wgt * h.x; acc.y += wgt * h.y;
                acc.z += wgt * h.z; acc.w += wgt * h.w;
            }
            orow[tid] = acc;
        }
    }
    if (blockIdx.x == 0 && tid == 0 && out_size >= (long long)B * S * D + B)
        out[(size_t)B * S * D + b] = (float)n;
}

// ---------------------------------------------------------------------------
extern "C" void kernel_launch(void* const* d_in, const int* in_sizes, int n_in,
                              void* d_out, int out_size) {
    const float* x      = (const float*)d_in[0];  // (B,S,D)
    const int*   lens   = (const int*)  d_in[1];  // (B,)
    const float* conv_w = (const float*)d_in[2];  // (D,D,3)
    const float* conv_b = (const float*)d_in[3];  // (D,)
    const float* lin_w  = (const float*)d_in[4];  // (1,D)
    const float* lin_b  = (const float*)d_in[5];  // (1,)

    const int B = in_sizes[1];
    const int D = in_sizes[4];
    const int S = in_sizes[0] / (B * D);
    float* out = (float*)d_out;

    {
        dim3 g1((D * 3 + 255) / 256, NCHUNK);
        k_fuse_part<<<g1, 256>>>(conv_w, lin_w, D);
        k_fuse_comb<<<(D * 3 + 255) / 256 + 1, 256>>>(conv_b, lin_w, lin_b, D);
    }
    {
        dim3 grid((S + 7) / 8, B);
        k_z<<<grid, 256>>>(x, S, D);
    }
    k_scan<<<B, 256>>>(lens, S);
    {
        dim3 grid((S + 3) / 4, B);
        k_emit<<<grid, D / 4>>>(x, out, B, S, D, (long long)out_size);
    }
}

// round 12
// speedup vs baseline: 1.3438x; 1.3438x over previous
#include <cuda_runtime.h>
#include <math.h>

// Problem shape: B=16, S=2048, D=768
#define MAXB 16
#define MAXS 2048
#define MAXD 768
#define NCHUNK 16   // o-dim chunks for fuse partials

// Scratch (device globals — no allocation allowed)
__device__ float g_part[NCHUNK * MAXD * 3];  // fuse partials [chunk][p]
__device__ float g_w2[MAXD * 3];             // fused conv*linear weights [i*3+k]
__device__ float g_c;                        // fused bias
__device__ float g_z0[MAXB * MAXS];          // per-row dot with w2[:,k]
__device__ float g_z1[MAXB * MAXS];
__device__ float g_z2[MAXB * MAXS];
__device__ float g_alpha[MAXB * MAXS];
__device__ int   g_Ft[MAXB * MAXS];          // fire time indices (compacted)
__device__ float g_Fa1[MAXB * MAXS];         // a1 at fire j
__device__ float g_Fa2[MAXB * MAXS];         // a2 at fire j
__device__ int   g_n[MAXB];

// ---------------------------------------------------------------------------
// Kernel 1a: partial fuse. grid = (9 p-blocks, NCHUNK o-chunks), 256 thr.
// ---------------------------------------------------------------------------
__global__ void k_fuse_part(const float* __restrict__ conv_w,
                            const float* __restrict__ lin_w, int D) {
    const int p = blockIdx.x * 256 + threadIdx.x;     // p = i*3+k
    const int P = D * 3;
    if (p >= P) return;
    const int ch = blockIdx.y;
    const int csz = D / NCHUNK;
    const int o0 = ch * csz;
    float acc = 0.f;
    #pragma unroll 4
    for (int o = o0; o < o0 + csz; o++)
        acc += lin_w[o] * conv_w[(size_t)o * P + p];
    g_part[ch * P + p] = acc;
}

// ---------------------------------------------------------------------------
// Kernel 1b: combine partials (fixed order) + c scalar.
// ---------------------------------------------------------------------------
__global__ void k_fuse_comb(const float* __restrict__ conv_b,
                            const float* __restrict__ lin_w,
                            const float* __restrict__ lin_b, int D) {
    const int P = D * 3;
    if ((int)blockIdx.x == (int)gridDim.x - 1) {
        __shared__ float red[256];
        float s = 0.f;
        for (int o = threadIdx.x; o < D; o += 256) s += lin_w[o] * conv_b[o];
        red[threadIdx.x] = s;
        __syncthreads();
        for (int st = 128; st > 0; st >>= 1) {
            if ((int)threadIdx.x < st) red[threadIdx.x] += red[threadIdx.x + st];
            __syncthreads();
        }
        if (threadIdx.x == 0) g_c = red[0] + lin_b[0];
    } else {
        int p = blockIdx.x * 256 + threadIdx.x;
        if (p < P) {
            float acc = 0.f;
            #pragma unroll
            for (int ch = 0; ch < NCHUNK; ch++) acc += g_part[ch * P + p];
            g_w2[p] = acc;
        }
    }
}

// ---------------------------------------------------------------------------
// Kernel 2: z_k[r] = dot(x[r], w2[:,k]). Warp per row, 8 warps/blk.
// ---------------------------------------------------------------------------
__global__ void k_z(const float* __restrict__ x, int S, int D) {
    __shared__ __align__(16) float sw2[3 * MAXD];
    for (int idx = threadIdx.x; idx < D * 3; idx += blockDim.x) {
        int i = idx / 3, k = idx - i * 3;
        sw2[k * D + i] = g_w2[idx];
    }
    __syncthreads();

    const int b = blockIdx.y;
    const int warp = threadIdx.x >> 5, lane = threadIdx.x & 31;
    const int r = blockIdx.x * 8 + warp;
    if (r >= S) return;

    const float4* xr  = (const float4*)(x + ((size_t)b * S + r) * D);
    const float4* w0  = (const float4*)(sw2);
    const float4* w1  = (const float4*)(sw2 + D);
    const float4* w2p = (const float4*)(sw2 + 2 * D);
    float a0 = 0.f, a1 = 0.f, a2 = 0.f;

    if (D == MAXD) {
        float4 xv[6];
        #pragma unroll
        for (int u = 0; u < 6; u++) xv[u] = xr[lane + 32 * u];
        #pragma unroll
        for (int u = 0; u < 6; u++) {
            const int m = lane + 32 * u;
            float4 uu = w0[m];
            a0 += uu.x * xv[u].x + uu.y * xv[u].y + uu.z * xv[u].z + uu.w * xv[u].w;
            float4 vv = w1[m];
            a1 += vv.x * xv[u].x + vv.y * xv[u].y + vv.z * xv[u].z + vv.w * xv[u].w;
            float4 ww = w2p[m];
            a2 += ww.x * xv[u].x + ww.y * xv[u].y + ww.z * xv[u].z + ww.w * xv[u].w;
        }
    } else {
        const int M = D >> 2;
        for (int m = lane; m < M; m += 32) {
            float4 xv = xr[m];
            float4 uu = w0[m];
            a0 += uu.x * xv.x + uu.y * xv.y + uu.z * xv.z + uu.w * xv.w;
            float4 vv = w1[m];
            a1 += vv.x * xv.x + vv.y * xv.y + vv.z * xv.z + vv.w * xv.w;
            float4 ww = w2p[m];
            a2 += ww.x * xv.x + ww.y * xv.y + ww.z * xv.z + ww.w * xv.w;
        }
    }
    #pragma unroll
    for (int o = 16; o > 0; o >>= 1) {
        a0 += __shfl_xor_sync(0xffffffffu, a0, o);
        a1 += __shfl_xor_sync(0xffffffffu, a1, o);
        a2 += __shfl_xor_sync(0xffffffffu, a2, o);
    }
    if (lane == 0) {
        size_t idx = (size_t)b * S + r;
        g_z0[idx] = a0; g_z1[idx] = a1; g_z2[idx] = a2;
    }
}

// ---------------------------------------------------------------------------
// Kernel 3: alpha — WIDE grid (back out of k_scan; the 16-block scan kernel
// was paying ~30 µs for this exact work on 16 SMs).
// alpha[b,t] = sigmoid(c + z0[t-1] + z1[t] + z2[t+1]), 0 if t >= len.
// ---------------------------------------------------------------------------
__global__ void k_comb(const int* __restrict__ lens, int B, int S) {
    int idx = blockIdx.x * 256 + threadIdx.x;
    if (idx >= B * S) return;
    int b = idx / S, t = idx - b * S;
    float a = 0.f;
    if (t < lens[b]) {
        float l = g_c + g_z1[idx];
        if (t > 0)     l += g_z0[idx - 1];
        if (t < S - 1) l += g_z2[idx + 1];
        a = 1.f / (1.f + expf(-l));
    }
    g_alpha[idx] = a;
}

// ---------------------------------------------------------------------------
// Short-recurrence chain step (validated R10/R11): on fire the reference's
// a2 = a - fl(1-aacc) equals fl(s1-1) up to 1 ulp (Sterbenz on [1,2)).
// ---------------------------------------------------------------------------
#define CHAINSTEP(aval)                                \
    {   float a   = (aval);                            \
        float s1  = aacc + a;                          \
        float sm1 = s1 - 1.0f;                         \
        bool fire = (s1 >= 1.0f);                      \
        BODY                                           \
        aacc = fire ? sm1 : s1;                        \
        bit++;                                         \
    }
#define CHAIN8(q)  CHAINSTEP((q).x) CHAINSTEP((q).y) CHAINSTEP((q).z) CHAINSTEP((q).w)
#define CHAIN32    { CHAIN8(v0) } { CHAIN8(v1) } { CHAIN8(v2) } { CHAIN8(v3) } \
                   { CHAIN8(v4) } { CHAIN8(v5) } { CHAIN8(v6) } { CHAIN8(v7) }

// ---------------------------------------------------------------------------
// Kernel 4: chunk-based CIF scan (validated R11), now WITHOUT alpha compute.
// One block/batch: load precomputed g_alpha (8KB), 64 parallel double chunk
// sums, 64-step serial fract() chain in double, parallel float replay for
// masks, popc prefix, replay for compacted records.
// ---------------------------------------------------------------------------
__global__ void k_scan(int S) {
    __shared__ __align__(16) float sa[MAXS];
    __shared__ double sSum[MAXS / 32];
    __shared__ float  sChk[MAXS / 32];
    __shared__ unsigned int sMask[MAXS / 32];
    __shared__ int    sNfb[MAXS / 32];
    const int b = blockIdx.x;
    const int base = b * S;
    const int NC = S >> 5;   // chunks of 32 (S multiple of 32)

    // Load alphas (vectorized; base is 32-float aligned)
    {
        const float4* src = (const float4*)(g_alpha + base);
        float4* dst = (float4*)sa;
        for (int m = threadIdx.x; m < (S >> 2); m += blockDim.x)
            dst[m] = src[m];
    }
    __syncthreads();

    // Per-chunk double sums (parallel, deterministic order)
    if ((int)threadIdx.x < NC) {
        const float* p = sa + (threadIdx.x << 5);
        double s = 0.0;
        #pragma unroll
        for (int u = 0; u < 32; u++) s += (double)p[u];
        sSum[threadIdx.x] = s;
    }
    __syncthreads();

    // Serial phase: 64 chunk steps in double (monotone sum => fract carries)
    if (threadIdx.x == 0) {
        double aacc = 0.0;
        for (int cb = 0; cb < NC; cb++) {
            sChk[cb] = (float)aacc;
            double t = aacc + sSum[cb];
            aacc = t - floor(t);
        }
    }
    __syncthreads();

    // Parallel float replay -> fire masks
    if ((int)threadIdx.x < NC) {
        const int cb = threadIdx.x;
        float aacc = sChk[cb];
        const float4* q = (const float4*)(sa + (cb << 5));
        float4 v0 = q[0], v1 = q[1], v2 = q[2], v3 = q[3];
        float4 v4 = q[4], v5 = q[5], v6 = q[6], v7 = q[7];
        unsigned int mask = 0u;
        int bit = 0;
        #define BODY mask |= fire ? (1u << bit) : 0u;
        CHAIN32
        #undef BODY
        sMask[cb] = mask;
    }
    __syncthreads();

    // Prefix counts
    if ((int)threadIdx.x < NC) {
        int cnt = 0;
        for (int j = 0; j < (int)threadIdx.x; j++) cnt += __popc(sMask[j]);
        sNfb[threadIdx.x] = cnt;
        if ((int)threadIdx.x == NC - 1)
            g_n[b] = cnt + __popc(sMask[NC - 1]);
    }
    __syncthreads();

    // Replay again, write compacted records (exact reference formulas)
    if ((int)threadIdx.x < NC) {
        const int cb = threadIdx.x;
        if (sMask[cb]) {
            float aacc = sChk[cb];
            int pos = base + sNfb[cb];
            const int t0c = cb << 5;
            const float4* q = (const float4*)(sa + t0c);
            float4 v0 = q[0], v1 = q[1], v2 = q[2], v3 = q[3];
            float4 v4 = q[4], v5 = q[5], v6 = q[6], v7 = q[7];
            int bit = 0;
            #define BODY if (fire) { float ra1 = 1.0f - aacc;      \
                                     float ra2 = a - ra1;          \
                                     g_Ft[pos] = t0c + bit;        \
                                     g_Fa1[pos] = ra1;             \
                                     g_Fa2[pos] = ra2; pos++; }
            CHAIN32
            #undef BODY
        }
    }
}

// ---------------------------------------------------------------------------
// Kernel 5: emit (R7-best config). Block (jb, b) handles 4 output rows.
// Row j < n: weighted sum over t in [F[j-1], F[j]]; rows >= n: zeros.
// ---------------------------------------------------------------------------
__global__ void k_emit(const float* __restrict__ x, float* __restrict__ out,
                       int B, int S, int D, long long out_size) {
    const int b = blockIdx.y;
    const int tid = threadIdx.x;
    const int n = g_n[b];
    const int base = b * S;
    const int j0 = blockIdx.x * 4;

    #pragma unroll
    for (int jj = 0; jj < 4; jj++) {
        const int j = j0 + jj;
        if (j >= S) break;
        float4* orow = (float4*)(out + ((size_t)b * S + j) * D);
        if (j >= n) {
            orow[tid] = make_float4(0.f, 0.f, 0.f, 0.f);
        } else {
            const int t1 = g_Ft[base + j];
            const int t0 = (j == 0) ? 0 : g_Ft[base + j - 1];
            const float wa1 = g_Fa1[base + j];
            const float wa2 = (j == 0) ? 0.f : g_Fa2[base + j - 1];
            float4 acc = make_float4(0.f, 0.f, 0.f, 0.f);
            #pragma unroll 4
            for (int t = t0; t <= t1; t++) {
                float wgt = (t == t1) ? wa1
                          : ((j > 0 && t == t0) ? wa2 : g_alpha[base + t]);
                const float4 h = ((const float4*)(x + ((size_t)b * S + t) * D))[tid];
                acc.x += wgt * h.x; acc.y += wgt * h.y;
                acc.z += wgt * h.z; acc.w += wgt * h.w;
            }
            orow[tid] = acc;
        }
    }
    if (blockIdx.x == 0 && tid == 0 && out_size >= (long long)B * S * D + B)
        out[(size_t)B * S * D + b] = (float)n;
}

// ---------------------------------------------------------------------------
extern "C" void kernel_launch(void* const* d_in, const int* in_sizes, int n_in,
                              void* d_out, int out_size) {
    const float* x      = (const float*)d_in[0];  // (B,S,D)
    const int*   lens   = (const int*)  d_in[1];  // (B,)
    const float* conv_w = (const float*)d_in[2];  // (D,D,3)
    const float* conv_b = (const float*)d_in[3];  // (D,)
    const float* lin_w  = (const float*)d_in[4];  // (1,D)
    const float* lin_b  = (const float*)d_in[5];  // (1,)

    const int B = in_sizes[1];
    const int D = in_sizes[4];
    const int S = in_sizes[0] / (B * D);
    float* out = (float*)d_out;

    {
        dim3 g1((D * 3 + 255) / 256, NCHUNK);
        k_fuse_part<<<g1, 256>>>(conv_w, lin_w, D);
        k_fuse_comb<<<(D * 3 + 255) / 256 + 1, 256>>>(conv_b, lin_w, lin_b, D);
    }
    {
        dim3 grid((S + 7) / 8, B);
        k_z<<<grid, 256>>>(x, S, D);
    }
    k_comb<<<(B * S + 255) / 256, 256>>>(lens, B, S);   // wide alpha pass
    k_scan<<<B, 256>>>(S);                               // 16-block scan only
    {
        dim3 grid((S + 3) / 4, B);
        k_emit<<<grid, D / 4>>>(x, out, B, S, D, (long long)out_size);
    }
}